// round 1
// baseline (speedup 1.0000x reference)
#include <cuda_runtime.h>
#include <cuda_bf16.h>
#include <math.h>

// Problem constants
#define BB 32
#define NN 2048
#define DD 256

#define L2_LAMDA 0.001f
#define RECONS_LAMDA 0.2f
#define LB_TH 0.01f

// GEMM tiling
#define BM 64
#define BN 64
#define BK 16
#define BMP 68   // padded row length for As (68 % 32 != 0, 68*4 bytes is 16B-multiple)

#define D_TILES (DD / BN)   // 4

// Scratch (no device allocation allowed -> __device__ globals)
__device__ float g_part[D_TILES * BB * NN];   // partial sum-of-squares per (dtile, b, n)
__device__ float g_rowterm[NN];               // l1[n] + 0.001*l2[n]

// ---------------------------------------------------------------------------
// Kernel 1: per-row stats of masked incidence matrix
// W[n,m] = inc[n,m] if inc[n,m] > LB_TH else 0
// g_rowterm[n] = max(W[n,:]) + L2_LAMDA * sqrt(sum(W[n,:]^2))
// ---------------------------------------------------------------------------
__global__ __launch_bounds__(256) void row_stats_kernel(const float* __restrict__ inc) {
    int n = blockIdx.x;
    int tid = threadIdx.x;
    const float* row = inc + (size_t)n * NN;

    float mx = 0.0f, sq = 0.0f;
    for (int m = tid; m < NN; m += 256) {
        float v = row[m];
        if (v > LB_TH) {
            mx = fmaxf(mx, v);   // masked values are positive -> abs == value
            sq += v * v;
        }
    }

    __shared__ float smx[256];
    __shared__ float ssq[256];
    smx[tid] = mx;
    ssq[tid] = sq;
    __syncthreads();
    for (int s = 128; s > 0; s >>= 1) {
        if (tid < s) {
            smx[tid] = fmaxf(smx[tid], smx[tid + s]);
            ssq[tid] += ssq[tid + s];
        }
        __syncthreads();
    }
    if (tid == 0) {
        g_rowterm[n] = smx[0] + L2_LAMDA * sqrtf(ssq[0]);
    }
}

// ---------------------------------------------------------------------------
// Kernel 2: fused diff GEMM
// For block (dtile, ntile, b):
//   diff[m, j] = sum_k cur[b, n0+m, k] * rproj[k, d0+j]
//              - sum_k W[n0+m, k]      * pre[b, k, d0+j]
// then g_part[dtile][b][n0+m] = sum_j diff[m, j]^2   (64-col slice)
// Register-tiled 64x64x16 SGEMM, 16x16 threads, 4x4 micro-tile per thread.
// ---------------------------------------------------------------------------
__global__ __launch_bounds__(256) void fused_diff_gemm(
    const float* __restrict__ cur,
    const float* __restrict__ pre,
    const float* __restrict__ rproj,
    const float* __restrict__ inc)
{
    __shared__ float As[BK][BMP];       // [k][m]
    __shared__ float Bs[BK][BN];        // [k][j]
    __shared__ float red[16][BM + 1];   // [tx][row] partial row sums

    const int tx = threadIdx.x;         // 0..15 (cols)
    const int ty = threadIdx.y;         // 0..15 (rows)
    const int tid = ty * 16 + tx;

    const int d0 = blockIdx.x * BN;
    const int n0 = blockIdx.y * BM;
    const int b  = blockIdx.z;

    float acc[4][4];
#pragma unroll
    for (int r = 0; r < 4; r++)
#pragma unroll
        for (int c = 0; c < 4; c++) acc[r][c] = 0.0f;

    // Load-thread mappings
    const int la_m  = tid / 4;          // 0..63  (row in tile)
    const int la_k4 = (tid % 4) * 4;    // 0,4,8,12 (k base, float4)
    const int lb_k  = tid / 16;         // 0..15
    const int lb_j  = (tid % 16) * 4;   // 0..60 step 4

    // ---------------- Phase A: + cur @ rproj  (K = DD) ----------------
    const float* curb = cur + (size_t)b * NN * DD;
    for (int k0 = 0; k0 < DD; k0 += BK) {
        // As[k][m] = cur[b, n0+m, k0+k]
        float4 va = *(const float4*)&curb[(size_t)(n0 + la_m) * DD + k0 + la_k4];
        As[la_k4 + 0][la_m] = va.x;
        As[la_k4 + 1][la_m] = va.y;
        As[la_k4 + 2][la_m] = va.z;
        As[la_k4 + 3][la_m] = va.w;
        // Bs[k][j] = rproj[k0+k, d0+j]
        float4 vb = *(const float4*)&rproj[(size_t)(k0 + lb_k) * DD + d0 + lb_j];
        *(float4*)&Bs[lb_k][lb_j] = vb;
        __syncthreads();

#pragma unroll
        for (int k = 0; k < BK; k++) {
            float4 af = *(const float4*)&As[k][ty * 4];
            float4 bf = *(const float4*)&Bs[k][tx * 4];
            float a[4] = {af.x, af.y, af.z, af.w};
            float bv[4] = {bf.x, bf.y, bf.z, bf.w};
#pragma unroll
            for (int r = 0; r < 4; r++)
#pragma unroll
                for (int c = 0; c < 4; c++)
                    acc[r][c] = fmaf(a[r], bv[c], acc[r][c]);
        }
        __syncthreads();
    }

    // ---------------- Phase B: - W @ pre  (K = NN) ----------------
    const float* preb = pre + (size_t)b * NN * DD;
    for (int k0 = 0; k0 < NN; k0 += BK) {
        // As[k][m] = mask(inc[n0+m, k0+k])
        float4 va = *(const float4*)&inc[(size_t)(n0 + la_m) * NN + k0 + la_k4];
        As[la_k4 + 0][la_m] = (va.x > LB_TH) ? va.x : 0.0f;
        As[la_k4 + 1][la_m] = (va.y > LB_TH) ? va.y : 0.0f;
        As[la_k4 + 2][la_m] = (va.z > LB_TH) ? va.z : 0.0f;
        As[la_k4 + 3][la_m] = (va.w > LB_TH) ? va.w : 0.0f;
        // Bs[k][j] = pre[b, k0+k, d0+j]
        float4 vb = *(const float4*)&preb[(size_t)(k0 + lb_k) * DD + d0 + lb_j];
        *(float4*)&Bs[lb_k][lb_j] = vb;
        __syncthreads();

#pragma unroll
        for (int k = 0; k < BK; k++) {
            float4 af = *(const float4*)&As[k][ty * 4];
            float4 bf = *(const float4*)&Bs[k][tx * 4];
            float a[4] = {af.x, af.y, af.z, af.w};
            float bv[4] = {bf.x, bf.y, bf.z, bf.w};
#pragma unroll
            for (int r = 0; r < 4; r++)
#pragma unroll
                for (int c = 0; c < 4; c++)
                    acc[r][c] = fmaf(-a[r], bv[c], acc[r][c]);
        }
        __syncthreads();
    }

    // ---------------- Row-wise sum of squares over this 64-col slice ----------------
#pragma unroll
    for (int r = 0; r < 4; r++) {
        float s = acc[r][0] * acc[r][0] + acc[r][1] * acc[r][1]
                + acc[r][2] * acc[r][2] + acc[r][3] * acc[r][3];
        red[tx][ty * 4 + r] = s;
    }
    __syncthreads();

    if (tid < BM) {
        float t = 0.0f;
#pragma unroll
        for (int x = 0; x < 16; x++) t += red[x][tid];   // fixed order: deterministic
        g_part[((size_t)blockIdx.x * BB + b) * NN + n0 + tid] = t;
    }
}

// ---------------------------------------------------------------------------
// Kernel 3: finalize per-batch loss
// out[b] = 0.2 * sum_n sqrt(sum_dtile g_part) + sum_n g_rowterm[n]
// ---------------------------------------------------------------------------
__global__ __launch_bounds__(256) void finalize_kernel(float* __restrict__ out) {
    int b = blockIdx.x;
    int tid = threadIdx.x;

    float srec = 0.0f, srow = 0.0f;
    for (int n = tid; n < NN; n += 256) {
        float t = g_part[((size_t)0 * BB + b) * NN + n]
                + g_part[((size_t)1 * BB + b) * NN + n]
                + g_part[((size_t)2 * BB + b) * NN + n]
                + g_part[((size_t)3 * BB + b) * NN + n];
        srec += sqrtf(t);
        srow += g_rowterm[n];
    }

    __shared__ float s1[256];
    __shared__ float s2[256];
    s1[tid] = srec;
    s2[tid] = srow;
    __syncthreads();
    for (int s = 128; s > 0; s >>= 1) {
        if (tid < s) { s1[tid] += s1[tid + s]; s2[tid] += s2[tid + s]; }
        __syncthreads();
    }
    if (tid == 0) {
        out[b] = RECONS_LAMDA * s1[0] + s2[0];
    }
}

// ---------------------------------------------------------------------------
extern "C" void kernel_launch(void* const* d_in, const int* in_sizes, int n_in,
                              void* d_out, int out_size) {
    // Identify inputs by size where unambiguous (robust to ordering surprises):
    // cur: B*N*D = 16777216, pre: 16777216, rproj: 65536, inc: 4194304
    const float* cur = nullptr;
    const float* pre = nullptr;
    const float* rproj = nullptr;
    const float* inc = nullptr;
    int big_seen = 0;
    for (int i = 0; i < n_in; i++) {
        if (in_sizes[i] == DD * DD) rproj = (const float*)d_in[i];
        else if (in_sizes[i] == NN * NN) inc = (const float*)d_in[i];
        else if (in_sizes[i] == BB * NN * DD) {
            if (big_seen == 0) cur = (const float*)d_in[i];
            else pre = (const float*)d_in[i];
            big_seen++;
        }
    }

    float* out = (float*)d_out;

    row_stats_kernel<<<NN, 256>>>(inc);
    fused_diff_gemm<<<dim3(D_TILES, NN / BM, BB), dim3(16, 16)>>>(cur, pre, rproj, inc);
    finalize_kernel<<<BB, 256>>>(out);

    // Reference returns (loss, incidence_m). If the harness concatenates tuple
    // outputs, pass incidence through after the B loss values.
    if (out_size >= BB + NN * NN) {
        cudaMemcpyAsync(out + BB, inc, (size_t)NN * NN * sizeof(float),
                        cudaMemcpyDeviceToDevice, 0);
    }
}

// round 3
// speedup vs baseline: 7.9366x; 7.9366x over previous
#include <cuda_runtime.h>
#include <cuda_bf16.h>
#include <math.h>
#include <stdint.h>

#define BB 32
#define NN 2048
#define DD 256

#define L2_LAMDA 0.001f
#define RECONS_LAMDA 0.2f
#define LB_TH 0.01f

// ---------------------------------------------------------------------------
// Device scratch (no allocations allowed)
// ---------------------------------------------------------------------------
__device__ __nv_bfloat16 g_cur_bf[(size_t)BB * NN * DD];   // [b][n][k]
__device__ __nv_bfloat16 g_preT[(size_t)BB * DD * NN];     // [b][d][n]  (transposed)
__device__ __nv_bfloat16 g_w_bf[(size_t)NN * NN];          // NEGATED masked incidence [n][m]
__device__ __nv_bfloat16 g_rT[DD * DD];                    // [j][k]     (transposed)
__device__ float g_rowterm[NN];
__device__ float g_part[2 * BB * NN];                      // [dtile][b][n]

// ---------------------------------------------------------------------------
// PTX helpers
// ---------------------------------------------------------------------------
__device__ __forceinline__ uint32_t smem_u32(const void* p) {
    uint32_t a;
    asm("{ .reg .u64 t; cvta.to.shared.u64 t, %1; cvt.u32.u64 %0, t; }"
        : "=r"(a) : "l"(p));
    return a;
}

__device__ __forceinline__ void cp16(uint32_t dst, const void* src) {
    asm volatile("cp.async.cg.shared.global [%0], [%1], 16;"
                 :: "r"(dst), "l"(src) : "memory");
}
#define CP_COMMIT() asm volatile("cp.async.commit_group;" ::: "memory")

__device__ __forceinline__ void ldsm_x4(uint32_t& r0, uint32_t& r1,
                                        uint32_t& r2, uint32_t& r3, uint32_t addr) {
    asm volatile("ldmatrix.sync.aligned.m8n8.x4.shared.b16 {%0,%1,%2,%3}, [%4];"
                 : "=r"(r0), "=r"(r1), "=r"(r2), "=r"(r3) : "r"(addr));
}

__device__ __forceinline__ void mma16816(float* d, const uint32_t* a, const uint32_t* b) {
    asm volatile(
        "mma.sync.aligned.m16n8k16.row.col.f32.bf16.bf16.f32 "
        "{%0,%1,%2,%3}, {%4,%5,%6,%7}, {%8,%9}, {%0,%1,%2,%3};"
        : "+f"(d[0]), "+f"(d[1]), "+f"(d[2]), "+f"(d[3])
        : "r"(a[0]), "r"(a[1]), "r"(a[2]), "r"(a[3]), "r"(b[0]), "r"(b[1]));
}

// SW128 swizzle: XOR 16B-chunk index with (row & 7) for 128B rows
#define SWZ(o) ((uint32_t)(o) ^ ((((uint32_t)(o)) >> 3) & 0x70))

// ---------------------------------------------------------------------------
// Conversion: cur -> bf16 (same layout)
// ---------------------------------------------------------------------------
__global__ __launch_bounds__(256) void conv_cur_kernel(const float4* __restrict__ src, int n4) {
    int i = blockIdx.x * blockDim.x + threadIdx.x;
    if (i >= n4) return;
    __nv_bfloat162* dst = (__nv_bfloat162*)g_cur_bf;
    float4 v = src[i];
    dst[2 * i]     = __floats2bfloat162_rn(v.x, v.y);
    dst[2 * i + 1] = __floats2bfloat162_rn(v.z, v.w);
}

// Transpose fp32 [R][C] -> bf16 [C][R]; which: 0 = g_preT, 1 = g_rT
__global__ __launch_bounds__(256) void transpose_kernel(const float* __restrict__ src,
                                                        int which, int R, int C) {
    __shared__ float t[32][33];
    const int c0 = blockIdx.x * 32;
    const int r0 = blockIdx.y * 32;
    const float* s = src + (size_t)blockIdx.z * R * C;
    __nv_bfloat16* d = ((which == 0) ? g_preT : g_rT) + (size_t)blockIdx.z * R * C;
    const int tx = threadIdx.x, ty = threadIdx.y;
#pragma unroll
    for (int i = 0; i < 4; i++)
        t[ty + i * 8][tx] = s[(size_t)(r0 + ty + i * 8) * C + c0 + tx];
    __syncthreads();
#pragma unroll
    for (int i = 0; i < 4; i++)
        d[(size_t)(c0 + ty + i * 8) * R + r0 + tx] = __float2bfloat16(t[tx][ty + i * 8]);
}

// Masked+negated bf16 incidence + per-row l1/l2 stats
__global__ __launch_bounds__(256) void conv_inc_kernel(const float* __restrict__ inc) {
    int n = blockIdx.x;
    int tid = threadIdx.x;
    const float4* row = (const float4*)(inc + (size_t)n * NN);
    __nv_bfloat162* wrow = (__nv_bfloat162*)(g_w_bf + (size_t)n * NN);

    float mx = 0.0f, sq = 0.0f;
    for (int i = tid; i < NN / 4; i += 256) {
        float4 v = row[i];
        float a = (v.x > LB_TH) ? v.x : 0.0f;
        float b = (v.y > LB_TH) ? v.y : 0.0f;
        float c = (v.z > LB_TH) ? v.z : 0.0f;
        float d = (v.w > LB_TH) ? v.w : 0.0f;
        mx = fmaxf(mx, fmaxf(fmaxf(a, b), fmaxf(c, d)));
        sq += a * a + b * b + c * c + d * d;
        wrow[2 * i]     = __floats2bfloat162_rn(-a, -b);
        wrow[2 * i + 1] = __floats2bfloat162_rn(-c, -d);
    }

    __shared__ float smx[256];
    __shared__ float ssq[256];
    smx[tid] = mx; ssq[tid] = sq;
    __syncthreads();
    for (int s = 128; s > 0; s >>= 1) {
        if (tid < s) {
            smx[tid] = fmaxf(smx[tid], smx[tid + s]);
            ssq[tid] += ssq[tid + s];
        }
        __syncthreads();
    }
    if (tid == 0) g_rowterm[n] = smx[0] + L2_LAMDA * sqrtf(ssq[0]);
}

// ---------------------------------------------------------------------------
// Main GEMM: per CTA (dtile, ntile, b) compute 128x128 tile of
//   diff = cur_b @ R + (-W) @ pre_b   (fp32 reg accum, bf16 HMMA)
// then per-row sum of squares -> g_part.
// A smem: [128 m][64 k] bf16 SW128; B smem: [128 n][64 k] bf16 SW128 (K-major,
// operands pre-transposed). ldmatrix non-trans for both, mma row.col.
// 8 warps: warp_m = w&3 (32 rows), warp_n = w>>2 (64 cols).
// ---------------------------------------------------------------------------
#define CHUNKS 36            // 4 (K=256, cur@R) + 32 (K=2048, W@pre)
#define BUF_BYTES 32768      // 16KB A + 16KB B
#define GEMM_SMEM (2 * BUF_BYTES)

__global__ __launch_bounds__(256, 2) void gemm_kernel() {
    extern __shared__ char smem[];
    const uint32_t sb = smem_u32(smem);
    const int tid = threadIdx.x;
    const int lane = tid & 31;
    const int w = tid >> 5;
    const int warp_m = w & 3;
    const int warp_n = w >> 2;

    const int dtile = blockIdx.x;           // 0..1
    const int ntile = blockIdx.y;           // 0..15
    const int b     = blockIdx.z;           // 0..31
    const int n0 = ntile * 128;
    const int d0 = dtile * 128;

    float acc[2][8][4];
#pragma unroll
    for (int mt = 0; mt < 2; mt++)
#pragma unroll
        for (int nt = 0; nt < 8; nt++)
#pragma unroll
            for (int i = 0; i < 4; i++) acc[mt][nt][i] = 0.0f;

    // ldmatrix per-lane row precompute
    uint32_t arowp[2], arx[2];
#pragma unroll
    for (int mt = 0; mt < 2; mt++) {
        int r = warp_m * 32 + mt * 16 + (lane & 15);
        arowp[mt] = r * 128;
        arx[mt] = (r & 7);
    }
    uint32_t browp[4], brx[4];
#pragma unroll
    for (int p = 0; p < 4; p++) {
        int r = warp_n * 64 + p * 16 + (lane & 7) + ((lane & 16) ? 8 : 0);
        browp[p] = r * 128;
        brx[p] = (r & 7);
    }
    const uint32_t achunk_hi = (lane >> 4);        // 0/1
    const uint32_t bchunk_hi = ((lane >> 3) & 1);  // 0/1

    // global load lambda-ish via macro: chunk c into buffer buf
    const __nv_bfloat16* curb = g_cur_bf + ((size_t)b * NN + n0) * DD;
    const __nv_bfloat16* wb   = g_w_bf + (size_t)n0 * NN;
    const __nv_bfloat16* rtb  = g_rT + (size_t)d0 * DD;
    const __nv_bfloat16* ptb  = g_preT + ((size_t)b * DD + d0) * NN;

#define LOAD_CHUNK(c, buf)                                                        \
    {                                                                             \
        const __nv_bfloat16 *Ap, *Bp; int lda, ldb, k0;                           \
        if ((c) < 4) { k0 = (c) * 64; Ap = curb; lda = DD; Bp = rtb; ldb = DD; }  \
        else { k0 = ((c) - 4) * 64; Ap = wb; lda = NN; Bp = ptb; ldb = NN; }      \
        const uint32_t sA = sb + (buf) * BUF_BYTES;                               \
        const uint32_t sB = sA + 16384;                                           \
        _Pragma("unroll")                                                         \
        for (int i = 0; i < 4; i++) {                                             \
            int o = tid + i * 256;                                                \
            int row = o >> 3, seg = o & 7;                                        \
            cp16(sA + SWZ(row * 128 + seg * 16),                                  \
                 Ap + (size_t)row * lda + k0 + seg * 8);                          \
        }                                                                         \
        _Pragma("unroll")                                                         \
        for (int i = 0; i < 4; i++) {                                             \
            int o = tid + i * 256;                                                \
            int row = o >> 3, seg = o & 7;                                        \
            cp16(sB + SWZ(row * 128 + seg * 16),                                  \
                 Bp + (size_t)row * ldb + k0 + seg * 8);                          \
        }                                                                         \
    }

    LOAD_CHUNK(0, 0);
    CP_COMMIT();

    for (int c = 0; c < CHUNKS; c++) {
        if (c + 1 < CHUNKS) {
            LOAD_CHUNK(c + 1, (c + 1) & 1);
            CP_COMMIT();
            asm volatile("cp.async.wait_group 1;" ::: "memory");
        } else {
            asm volatile("cp.async.wait_group 0;" ::: "memory");
        }
        __syncthreads();

        const uint32_t sA = sb + (c & 1) * BUF_BYTES;
        const uint32_t sB = sA + 16384;

#pragma unroll
        for (int s = 0; s < 4; s++) {
            uint32_t a[2][4];
#pragma unroll
            for (int mt = 0; mt < 2; mt++) {
                uint32_t ch = s * 2 + achunk_hi;
                ldsm_x4(a[mt][0], a[mt][1], a[mt][2], a[mt][3],
                        sA + arowp[mt] + ((ch ^ arx[mt]) << 4));
            }
            uint32_t bf[8][2];
#pragma unroll
            for (int p = 0; p < 4; p++) {
                uint32_t ch = s * 2 + bchunk_hi;
                ldsm_x4(bf[2 * p][0], bf[2 * p][1], bf[2 * p + 1][0], bf[2 * p + 1][1],
                        sB + browp[p] + ((ch ^ brx[p]) << 4));
            }
#pragma unroll
            for (int mt = 0; mt < 2; mt++)
#pragma unroll
                for (int nt = 0; nt < 8; nt++)
                    mma16816(acc[mt][nt], a[mt], bf[nt]);
        }
        __syncthreads();
    }

    // ------------- epilogue: per-row sum of squares -------------
    __shared__ float red[128][2];
#pragma unroll
    for (int mt = 0; mt < 2; mt++) {
        float s0 = 0.0f, s1 = 0.0f;
#pragma unroll
        for (int nt = 0; nt < 8; nt++) {
            s0 = fmaf(acc[mt][nt][0], acc[mt][nt][0], s0);
            s0 = fmaf(acc[mt][nt][1], acc[mt][nt][1], s0);
            s1 = fmaf(acc[mt][nt][2], acc[mt][nt][2], s1);
            s1 = fmaf(acc[mt][nt][3], acc[mt][nt][3], s1);
        }
        // reduce across the 4 lanes of the quad (same row, different cols)
        s0 += __shfl_xor_sync(0xFFFFFFFF, s0, 1);
        s0 += __shfl_xor_sync(0xFFFFFFFF, s0, 2);
        s1 += __shfl_xor_sync(0xFFFFFFFF, s1, 1);
        s1 += __shfl_xor_sync(0xFFFFFFFF, s1, 2);
        if ((lane & 3) == 0) {
            int r = warp_m * 32 + mt * 16 + (lane >> 2);
            red[r][warp_n] = s0;
            red[r + 8][warp_n] = s1;
        }
    }
    __syncthreads();
    if (tid < 128) {
        float t = red[tid][0] + red[tid][1];
        g_part[((size_t)dtile * BB + b) * NN + n0 + tid] = t;
    }
}

// ---------------------------------------------------------------------------
// Finalize: out[b] = 0.2 * sum_n sqrt(part0 + part1) + sum_n rowterm
// ---------------------------------------------------------------------------
__global__ __launch_bounds__(256) void finalize_kernel(float* __restrict__ out) {
    int b = blockIdx.x;
    int tid = threadIdx.x;
    float srec = 0.0f, srow = 0.0f;
    for (int n = tid; n < NN; n += 256) {
        float t = g_part[((size_t)0 * BB + b) * NN + n]
                + g_part[((size_t)1 * BB + b) * NN + n];
        srec += sqrtf(t);
        srow += g_rowterm[n];
    }
    __shared__ float s1[256];
    __shared__ float s2[256];
    s1[tid] = srec; s2[tid] = srow;
    __syncthreads();
    for (int s = 128; s > 0; s >>= 1) {
        if (tid < s) { s1[tid] += s1[tid + s]; s2[tid] += s2[tid + s]; }
        __syncthreads();
    }
    if (tid == 0) out[b] = RECONS_LAMDA * s1[0] + s2[0];
}

// ---------------------------------------------------------------------------
extern "C" void kernel_launch(void* const* d_in, const int* in_sizes, int n_in,
                              void* d_out, int out_size) {
    const float* cur = nullptr;
    const float* pre = nullptr;
    const float* rproj = nullptr;
    const float* inc = nullptr;
    int big_seen = 0;
    for (int i = 0; i < n_in; i++) {
        if (in_sizes[i] == DD * DD) rproj = (const float*)d_in[i];
        else if (in_sizes[i] == NN * NN) inc = (const float*)d_in[i];
        else if (in_sizes[i] == BB * NN * DD) {
            if (big_seen == 0) cur = (const float*)d_in[i];
            else pre = (const float*)d_in[i];
            big_seen++;
        }
    }
    float* out = (float*)d_out;

    cudaFuncSetAttribute(gemm_kernel, cudaFuncAttributeMaxDynamicSharedMemorySize, GEMM_SMEM);

    const int n4_big = BB * NN * DD / 4;
    conv_cur_kernel<<<n4_big / 256, 256>>>((const float4*)cur, n4_big);
    transpose_kernel<<<dim3(DD / 32, NN / 32, BB), dim3(32, 8)>>>(pre, 0, NN, DD);
    transpose_kernel<<<dim3(DD / 32, DD / 32, 1), dim3(32, 8)>>>(rproj, 1, DD, DD);
    conv_inc_kernel<<<NN, 256>>>(inc);

    gemm_kernel<<<dim3(2, 16, BB), 256, GEMM_SMEM>>>();
    finalize_kernel<<<BB, 256>>>(out);

    if (out_size >= BB + NN * NN) {
        cudaMemcpyAsync(out + BB, inc, (size_t)NN * NN * sizeof(float),
                        cudaMemcpyDeviceToDevice, 0);
    }
}